// round 13
// baseline (speedup 1.0000x reference)
#include <cuda_runtime.h>
#include <cuda_bf16.h>
#include <cuda_fp16.h>
#include <cstdint>

#define NN 100000
#define NE 1600000
#define KP 136   // padded K stride (bf16): row stride 68 words -> ldmatrix conflict-free

// ---------------- device scratch ----------------
__device__ __half g_y[NN * 128];     // neighbor projection, fp16
__device__ __half g_s[NN * 128];     // self projection + bias, fp16
__device__ __half g_act[NN * 128];   // inter-layer activation, fp16
__device__ __nv_bfloat16 g_w1h[256 * 128], g_w1l[256 * 128];
__device__ __nv_bfloat16 g_w2h[256 * 128], g_w2l[256 * 128];
__device__ __nv_bfloat16 g_w3h[128 * 128], g_w3l[128 * 128];
__device__ float g_invdeg[NN];
__device__ int   g_rowptr[NN + 1];
__device__ int   g_cnt[NN];          // zero at entry of every run (drained by k_fill)
__device__ int   g_tscan[NN];
__device__ int   g_bsum[128];
__device__ int   g_esrc[NE];

__device__ __forceinline__ uint32_t smem_u32(const void* p) {
    uint32_t a;
    asm("{ .reg .u64 t; cvta.to.shared.u64 t, %1; cvt.u32.u64 %0, t; }" : "=r"(a) : "l"(p));
    return a;
}

// ---------------- weight prep only (feature split now lives in GEMM-1 staging) ----------------
__global__ void k_prepW(const float* __restrict__ Wn1, const float* __restrict__ Ws1,
                        const float* __restrict__ Wn2, const float* __restrict__ Ws2,
                        const float* __restrict__ Wn3, const float* __restrict__ Ws3,
                        __nv_bfloat16* __restrict__ w1h, __nv_bfloat16* __restrict__ w1l,
                        __nv_bfloat16* __restrict__ w2h, __nv_bfloat16* __restrict__ w2l,
                        __nv_bfloat16* __restrict__ w3h, __nv_bfloat16* __restrict__ w3l) {
    int idx = blockIdx.x * blockDim.x + threadIdx.x;
    if (idx >= 81920) return;
    const float* Wn;
    const float* Ws;
    __nv_bfloat16 *oh, *ol;
    int wi, C;
    if (idx < 32768) {
        wi = idx; Wn = Wn1; Ws = Ws1; oh = w1h; ol = w1l; C = 128;
    } else if (idx < 65536) {
        wi = idx - 32768; Wn = Wn2; Ws = Ws2; oh = w2h; ol = w2l; C = 128;
    } else {
        wi = idx - 65536; Wn = Wn3; Ws = Ws3; oh = w3h; ol = w3l; C = 40;
    }
    int n = wi >> 7, k = wi & 127;
    float f = 0.f;
    if (n < C) f = Wn[k * C + n];
    else if (n < 2 * C) f = Ws[k * C + (n - C)];
    __nv_bfloat16 h = __float2bfloat16(f);
    oh[wi] = h;
    ol[wi] = __float2bfloat16(f - __bfloat162float(h));
}

// ---------------- CSR chain ----------------
__global__ void k_count(const int* __restrict__ dst) {
    int e = blockIdx.x * blockDim.x + threadIdx.x;
    if (e < NE) atomicAdd(&g_cnt[dst[e]], 1);
}
__global__ void k_scan1() {
    __shared__ int wsum[32];
    int i = blockIdx.x * 1024 + threadIdx.x;
    int lane = threadIdx.x & 31, wid = threadIdx.x >> 5;
    int v = (i < NN) ? g_cnt[i] : 0;
    int x = v;
#pragma unroll
    for (int o = 1; o < 32; o <<= 1) {
        int t = __shfl_up_sync(0xffffffffu, x, o);
        if (lane >= o) x += t;
    }
    if (lane == 31) wsum[wid] = x;
    __syncthreads();
    if (wid == 0) {
        int w = wsum[lane];
#pragma unroll
        for (int o = 1; o < 32; o <<= 1) {
            int t = __shfl_up_sync(0xffffffffu, w, o);
            if (lane >= o) w += t;
        }
        wsum[lane] = w;
    }
    __syncthreads();
    int off = wid ? wsum[wid - 1] : 0;
    int inc = x + off;
    if (i < NN) g_tscan[i] = inc;
    if (threadIdx.x == 1023) g_bsum[blockIdx.x] = inc;   // raw block total
}
__global__ void k_scan3() {
    __shared__ int pre;
    int t = threadIdx.x;
    int blk = (blockIdx.x * 256) >> 10;   // superblock index (constant per block)
    if (t == 0) pre = 0;
    __syncthreads();
    int contrib = (t < blk) ? g_bsum[t] : 0;   // blk <= 98 < 256
#pragma unroll
    for (int o = 16; o > 0; o >>= 1) contrib += __shfl_down_sync(0xffffffffu, contrib, o);
    if ((t & 31) == 0 && contrib) atomicAdd(&pre, contrib);
    __syncthreads();
    int i = blockIdx.x * 256 + t;
    if (i < NN) {
        g_rowptr[i + 1] = g_tscan[i] + pre;
        if (i == 0) g_rowptr[0] = 0;
        int d = g_cnt[i];
        g_invdeg[i] = 1.0f / (float)(d > 0 ? d : 1);
    }
}
__global__ void k_fill(const int* __restrict__ src, const int* __restrict__ dst) {
    int e = blockIdx.x * blockDim.x + threadIdx.x;
    if (e < NE) {
        int d = dst[e];
        int p = g_rowptr[d] + atomicSub(&g_cnt[d], 1) - 1;
        g_esrc[p] = src[e];
    }
}

// ---------------- mma.sync bf16 dual GEMM ----------------
__device__ __forceinline__ void mma_bf16(float (&c)[4], const uint32_t (&a)[4],
                                         const uint32_t b0, const uint32_t b1) {
    asm volatile(
        "mma.sync.aligned.m16n8k16.row.col.f32.bf16.bf16.f32 "
        "{%0,%1,%2,%3}, {%4,%5,%6,%7}, {%8,%9}, {%0,%1,%2,%3};\n"
        : "+f"(c[0]), "+f"(c[1]), "+f"(c[2]), "+f"(c[3])
        : "r"(a[0]), "r"(a[1]), "r"(a[2]), "r"(a[3]), "r"(b0), "r"(b1));
}
__device__ __forceinline__ void ldsm_x4(uint32_t (&r)[4], uint32_t addr) {
    asm volatile("ldmatrix.sync.aligned.m8n8.x4.shared.b16 {%0,%1,%2,%3}, [%4];"
                 : "=r"(r[0]), "=r"(r[1]), "=r"(r[2]), "=r"(r[3]) : "r"(addr));
}
__device__ __forceinline__ void split2(float a, float b, uint32_t& hw, uint32_t& lw) {
    __nv_bfloat16 h0 = __float2bfloat16(a), h1 = __float2bfloat16(b);
    __nv_bfloat162 hp(h0, h1);
    __nv_bfloat162 lp(__float2bfloat16(a - __bfloat162float(h0)),
                      __float2bfloat16(b - __bfloat162float(h1)));
    hw = *(uint32_t*)&hp;
    lw = *(uint32_t*)&lp;
}

// MODE 0: A is fp32 (layer-1 features) -> split in staging (identical values to pre-split)
// MODE 1: A is fp16 activations -> split in staging (exact: 11 = 8+3 mantissa bits)
template <int MODE>
__global__ __launch_bounds__(256, 2) void k_gemm_mma(
    const float* __restrict__ xf, const __half* __restrict__ xa,
    const __nv_bfloat16* __restrict__ wh, const __nv_bfloat16* __restrict__ wl,
    const float* __restrict__ bias, int C,
    __half* __restrict__ y, __half* __restrict__ s) {
    extern __shared__ __nv_bfloat16 smarr[];
    __nv_bfloat16* Ah = smarr;
    __nv_bfloat16* Al = Ah + 128 * KP;
    __nv_bfloat16* Bh = Al + 128 * KP;
    __nv_bfloat16* Bl = Bh + 64 * KP;

    int tid = threadIdx.x;
    int row0 = blockIdx.x * 128;
    int col0 = blockIdx.y * 64;

    for (int idx = tid; idx < 128 * 16; idx += 256) {
        int r = idx >> 4, k = (idx & 15) << 3;
        int grow = row0 + r;
        uint4 vh = make_uint4(0, 0, 0, 0), vl = vh;
        uint32_t* ph = (uint32_t*)&vh;
        uint32_t* pl = (uint32_t*)&vl;
        if (grow < NN) {
            if (MODE == 0) {
                float4 f0 = *(const float4*)(xf + grow * 128 + k);
                float4 f1 = *(const float4*)(xf + grow * 128 + k + 4);
                split2(f0.x, f0.y, ph[0], pl[0]);
                split2(f0.z, f0.w, ph[1], pl[1]);
                split2(f1.x, f1.y, ph[2], pl[2]);
                split2(f1.z, f1.w, ph[3], pl[3]);
            } else {
                uint4 va = *(const uint4*)(xa + grow * 128 + k);   // 8 halves
                uint32_t* pa = (uint32_t*)&va;
#pragma unroll
                for (int w = 0; w < 4; w++) {
                    float2 f = __half22float2(*(__half2*)&pa[w]);
                    split2(f.x, f.y, ph[w], pl[w]);
                }
            }
        }
        *(uint4*)(Ah + r * KP + k) = vh;
        *(uint4*)(Al + r * KP + k) = vl;
    }
    for (int idx = tid; idx < 64 * 16; idx += 256) {
        int n = idx >> 4, k = (idx & 15) << 3;
        *(uint4*)(Bh + n * KP + k) = *(const uint4*)(wh + (col0 + n) * 128 + k);
        *(uint4*)(Bl + n * KP + k) = *(const uint4*)(wl + (col0 + n) * 128 + k);
    }
    __syncthreads();

    int wid = tid >> 5, lane = tid & 31;
    int mbase = (wid >> 1) * 32;
    int nbase = (wid & 1) * 32;
    int r4 = lane >> 2, tg = lane & 3;

    uint32_t aBase = smem_u32(Ah);
    uint32_t alBase = smem_u32(Al);
    uint32_t bBase = smem_u32(Bh);
    uint32_t blBase = smem_u32(Bl);

    int aRow = mbase + (lane & 15);
    int aOff = aRow * KP + ((lane >> 4) << 3);
    int q = lane >> 3;
    int bRow = nbase + ((q >> 1) << 3) + (lane & 7);
    int bOff = bRow * KP + ((q & 1) << 3);

    float acc[2][4][4];
#pragma unroll
    for (int mi = 0; mi < 2; mi++)
#pragma unroll
        for (int ni = 0; ni < 4; ni++)
#pragma unroll
            for (int c = 0; c < 4; c++) acc[mi][ni][c] = 0.f;

#pragma unroll
    for (int kc = 0; kc < 8; kc++) {
        int k0 = kc * 16;
        uint32_t ah[2][4], al[2][4];
        ldsm_x4(ah[0], aBase + (aOff + k0) * 2);
        ldsm_x4(ah[1], aBase + (aOff + 16 * KP + k0) * 2);
        ldsm_x4(al[0], alBase + (aOff + k0) * 2);
        ldsm_x4(al[1], alBase + (aOff + 16 * KP + k0) * 2);
        uint32_t bh01[4], bh23[4], bl01[4], bl23[4];
        ldsm_x4(bh01, bBase + (bOff + k0) * 2);
        ldsm_x4(bh23, bBase + (bOff + 16 * KP + k0) * 2);
        ldsm_x4(bl01, blBase + (bOff + k0) * 2);
        ldsm_x4(bl23, blBase + (bOff + 16 * KP + k0) * 2);
#pragma unroll
        for (int mi = 0; mi < 2; mi++) {
            mma_bf16(acc[mi][0], ah[mi], bh01[0], bh01[1]);
            mma_bf16(acc[mi][1], ah[mi], bh01[2], bh01[3]);
            mma_bf16(acc[mi][2], ah[mi], bh23[0], bh23[1]);
            mma_bf16(acc[mi][3], ah[mi], bh23[2], bh23[3]);
            mma_bf16(acc[mi][0], al[mi], bh01[0], bh01[1]);
            mma_bf16(acc[mi][1], al[mi], bh01[2], bh01[3]);
            mma_bf16(acc[mi][2], al[mi], bh23[0], bh23[1]);
            mma_bf16(acc[mi][3], al[mi], bh23[2], bh23[3]);
            mma_bf16(acc[mi][0], ah[mi], bl01[0], bl01[1]);
            mma_bf16(acc[mi][1], ah[mi], bl01[2], bl01[3]);
            mma_bf16(acc[mi][2], ah[mi], bl23[0], bl23[1]);
            mma_bf16(acc[mi][3], ah[mi], bl23[2], bl23[3]);
        }
    }

    // epilogue: y -> fp16, s -> fp16 (bias added in fp32)
#pragma unroll
    for (int mi = 0; mi < 2; mi++) {
#pragma unroll
        for (int ni = 0; ni < 4; ni++) {
            int grow0 = row0 + mbase + mi * 16 + r4;
            int cc = col0 + nbase + ni * 8 + tg * 2;
            if (cc >= 2 * C) continue;
#pragma unroll
            for (int half = 0; half < 2; half++) {
                int grow = grow0 + half * 8;
                if (grow >= NN) continue;
                float v0 = acc[mi][ni][half * 2 + 0];
                float v1 = acc[mi][ni][half * 2 + 1];
                if (cc < C) {
                    __half2 hv = __floats2half2_rn(v0, v1);
                    *(uint32_t*)(y + grow * C + cc) = *(uint32_t*)&hv;
                } else {
                    int c = cc - C;
                    __half2 hv = __floats2half2_rn(v0 + bias[c], v1 + bias[c + 1]);
                    *(uint32_t*)(s + grow * C + c) = *(uint32_t*)&hv;
                }
            }
        }
    }
}

// ---------------- gather (fp16 y) + finalize (F=128) -> fp16 activation ----------------
__global__ void k_aggfin128(const uint2* __restrict__ y2, const uint2* __restrict__ s2,
                            uint2* __restrict__ act2) {
    int n = (blockIdx.x * blockDim.x + threadIdx.x) >> 5;
    int lane = threadIdx.x & 31;
    if (n >= NN) return;
    int r0 = g_rowptr[n], r1 = g_rowptr[n + 1];
    float4 acc = make_float4(0.f, 0.f, 0.f, 0.f);
    for (int base = r0; base < r1; base += 32) {
        int idx = base + lane;
        int sid = (idx < r1) ? g_esrc[idx] : 0;
        int m = r1 - base;
        if (m > 32) m = 32;
#pragma unroll 4
        for (int j = 0; j < m; j++) {
            int sn = __shfl_sync(0xffffffffu, sid, j);
            uint2 v = y2[sn * 32 + lane];
            float2 p0 = __half22float2(*(__half2*)&v.x);
            float2 p1 = __half22float2(*(__half2*)&v.y);
            acc.x += p0.x; acc.y += p0.y; acc.z += p1.x; acc.w += p1.y;
        }
    }
    float id = g_invdeg[n];
    uint2 sv = s2[n * 32 + lane];
    float2 s01 = __half22float2(*(__half2*)&sv.x);
    float2 s23 = __half22float2(*(__half2*)&sv.y);
    float4 o;
    o.x = fmaxf(s01.x + acc.x * id, 0.f);
    o.y = fmaxf(s01.y + acc.y * id, 0.f);
    o.z = fmaxf(s23.x + acc.z * id, 0.f);
    o.w = fmaxf(s23.y + acc.w * id, 0.f);
    __half2 a01 = __floats2half2_rn(o.x, o.y);
    __half2 a23 = __floats2half2_rn(o.z, o.w);
    act2[n * 32 + lane] = make_uint2(*(uint32_t*)&a01, *(uint32_t*)&a23);
}

// ---------------- gather (fp16 y) + finalize (F=40) ----------------
__global__ void k_aggfin40(const uint32_t* __restrict__ y32, const uint32_t* __restrict__ s32,
                           float* __restrict__ out) {
    int n = (blockIdx.x * blockDim.x + threadIdx.x) >> 5;
    int lane = threadIdx.x & 31;
    if (n >= NN) return;
    int r0 = g_rowptr[n], r1 = g_rowptr[n + 1];
    float2 acc = make_float2(0.f, 0.f);
    for (int base = r0; base < r1; base += 32) {
        int idx = base + lane;
        int sid = (idx < r1) ? g_esrc[idx] : 0;
        int m = r1 - base;
        if (m > 32) m = 32;
#pragma unroll 4
        for (int j = 0; j < m; j++) {
            int sn = __shfl_sync(0xffffffffu, sid, j);
            if (lane < 20) {
                uint32_t v = y32[sn * 20 + lane];
                float2 p = __half22float2(*(__half2*)&v);
                acc.x += p.x; acc.y += p.y;
            }
        }
    }
    if (lane < 20) {
        float id = g_invdeg[n];
        uint32_t sv = s32[n * 20 + lane];
        float2 sp = __half22float2(*(__half2*)&sv);
        float2 o = make_float2(sp.x + acc.x * id, sp.y + acc.y * id);
        *(float2*)(out + n * 40 + lane * 2) = o;
    }
}

// ---------------- launch ----------------
extern "C" void kernel_launch(void* const* d_in, const int* in_sizes, int n_in,
                              void* d_out, int out_size) {
    const float* feat = (const float*)d_in[0];
    const int* src = (const int*)d_in[1];
    const int* dst = (const int*)d_in[2];
    const float* Ws1 = (const float*)d_in[3];
    const float* Wn1 = (const float*)d_in[4];
    const float* b1  = (const float*)d_in[5];
    const float* Ws2 = (const float*)d_in[6];
    const float* Wn2 = (const float*)d_in[7];
    const float* b2  = (const float*)d_in[8];
    const float* Ws3 = (const float*)d_in[9];
    const float* Wn3 = (const float*)d_in[10];
    const float* b3  = (const float*)d_in[11];
    float* out = (float*)d_out;

    __half *py, *ps, *pa;
    __nv_bfloat16 *pw1h, *pw1l, *pw2h, *pw2l, *pw3h, *pw3l;
    cudaGetSymbolAddress((void**)&py, g_y);
    cudaGetSymbolAddress((void**)&ps, g_s);
    cudaGetSymbolAddress((void**)&pa, g_act);
    cudaGetSymbolAddress((void**)&pw1h, g_w1h);
    cudaGetSymbolAddress((void**)&pw1l, g_w1l);
    cudaGetSymbolAddress((void**)&pw2h, g_w2h);
    cudaGetSymbolAddress((void**)&pw2l, g_w2l);
    cudaGetSymbolAddress((void**)&pw3h, g_w3h);
    cudaGetSymbolAddress((void**)&pw3l, g_w3l);

    const int SMEM = (128 + 128 + 64 + 64) * KP * 2;  // 104448
    cudaFuncSetAttribute(k_gemm_mma<0>, cudaFuncAttributeMaxDynamicSharedMemorySize, SMEM);
    cudaFuncSetAttribute(k_gemm_mma<1>, cudaFuncAttributeMaxDynamicSharedMemorySize, SMEM);

    int nbE = (NE + 255) / 256;
    int nbScan = (NN + 1023) / 1024;
    int gRows = (NN + 127) / 128;   // 782
    int gAgg = (NN + 7) / 8;

    // side stream for CSR chain
    cudaStream_t s1;
    cudaStreamCreate(&s1);
    cudaEvent_t e0, e1;
    cudaEventCreateWithFlags(&e0, cudaEventDisableTiming);
    cudaEventCreateWithFlags(&e1, cudaEventDisableTiming);

    cudaEventRecord(e0, 0);
    cudaStreamWaitEvent(s1, e0, 0);

    k_count<<<nbE, 256, 0, s1>>>(dst);
    k_scan1<<<nbScan, 1024, 0, s1>>>();
    k_scan3<<<(NN + 255) / 256, 256, 0, s1>>>();
    k_fill<<<nbE, 256, 0, s1>>>(src, dst);
    cudaEventRecord(e1, s1);

    // main stream: weight prep (tiny) + layer-1 GEMM straight from fp32 features
    k_prepW<<<(81920 + 255) / 256, 256>>>(Wn1, Ws1, Wn2, Ws2, Wn3, Ws3,
                                          pw1h, pw1l, pw2h, pw2l, pw3h, pw3l);
    k_gemm_mma<0><<<dim3(gRows, 4), 256, SMEM>>>(feat, nullptr,
                                                 pw1h, pw1l, b1, 128, py, ps);

    cudaStreamWaitEvent(0, e1, 0);

    k_aggfin128<<<gAgg, 256>>>((const uint2*)py, (const uint2*)ps, (uint2*)pa);
    // layer 2 (fp16 activations, in-staging split)
    k_gemm_mma<1><<<dim3(gRows, 4), 256, SMEM>>>(nullptr, pa,
                                                 pw2h, pw2l, b2, 128, py, ps);
    k_aggfin128<<<gAgg, 256>>>((const uint2*)py, (const uint2*)ps, (uint2*)pa);
    // layer 3
    k_gemm_mma<1><<<dim3(gRows, 2), 256, SMEM>>>(nullptr, pa,
                                                 pw3h, pw3l, b3, 40, py, ps);
    k_aggfin40<<<gAgg, 256>>>((const uint32_t*)py, (const uint32_t*)ps, out);
}

// round 15
// speedup vs baseline: 1.4427x; 1.4427x over previous
#include <cuda_runtime.h>
#include <cuda_bf16.h>
#include <cuda_fp16.h>
#include <cstdint>

#define NN 100000
#define NE 1600000
#define KP 136   // padded K stride (bf16): row stride 68 words -> ldmatrix conflict-free

// ---------------- device scratch ----------------
__device__ __half g_y[NN * 128];     // neighbor projection, fp16
__device__ __half g_s[NN * 128];     // self projection + bias, fp16
__device__ __half g_act[NN * 128];   // inter-layer activation, fp16
__device__ __nv_bfloat16 g_xh[NN * 128];   // layer-1 input split (from fp32 features)
__device__ __nv_bfloat16 g_xl[NN * 128];
__device__ __nv_bfloat16 g_w1h[256 * 128], g_w1l[256 * 128];
__device__ __nv_bfloat16 g_w2h[256 * 128], g_w2l[256 * 128];
__device__ __nv_bfloat16 g_w3h[128 * 128], g_w3l[128 * 128];
__device__ float g_invdeg[NN];
__device__ int   g_rowptr[NN + 1];
__device__ int   g_cnt[NN];          // zero at entry of every run (reset in k_scan3)
__device__ int   g_eidx[NE];         // per-edge intra-row slot (recorded during count)
__device__ int   g_tscan[NN];
__device__ int   g_bsum[128];
__device__ int   g_esrc[NE];

__device__ __forceinline__ uint32_t smem_u32(const void* p) {
    uint32_t a;
    asm("{ .reg .u64 t; cvta.to.shared.u64 t, %1; cvt.u32.u64 %0, t; }" : "=r"(a) : "l"(p));
    return a;
}

// ---------------- front: weight split + feature split ----------------
__global__ void k_split(const float4* __restrict__ x4, uint2* __restrict__ xh2,
                        uint2* __restrict__ xl2,
                        const float* __restrict__ Wn1, const float* __restrict__ Ws1,
                        const float* __restrict__ Wn2, const float* __restrict__ Ws2,
                        const float* __restrict__ Wn3, const float* __restrict__ Ws3,
                        __nv_bfloat16* __restrict__ w1h, __nv_bfloat16* __restrict__ w1l,
                        __nv_bfloat16* __restrict__ w2h, __nv_bfloat16* __restrict__ w2l,
                        __nv_bfloat16* __restrict__ w3h, __nv_bfloat16* __restrict__ w3l) {
    int idx = blockIdx.x * blockDim.x + threadIdx.x;
    if (idx < NN * 32) {
        float4 v = x4[idx];
        __nv_bfloat16 hx = __float2bfloat16(v.x), hy = __float2bfloat16(v.y);
        __nv_bfloat16 hz = __float2bfloat16(v.z), hw = __float2bfloat16(v.w);
        __nv_bfloat162 h01(hx, hy), h23(hz, hw);
        __nv_bfloat162 l01(__float2bfloat16(v.x - __bfloat162float(hx)),
                           __float2bfloat16(v.y - __bfloat162float(hy)));
        __nv_bfloat162 l23(__float2bfloat16(v.z - __bfloat162float(hz)),
                           __float2bfloat16(v.w - __bfloat162float(hw)));
        xh2[idx] = make_uint2(*(uint32_t*)&h01, *(uint32_t*)&h23);
        xl2[idx] = make_uint2(*(uint32_t*)&l01, *(uint32_t*)&l23);
    }
    if (idx < 81920) {
        const float* Wn;
        const float* Ws;
        __nv_bfloat16 *oh, *ol;
        int wi, C;
        if (idx < 32768) {
            wi = idx; Wn = Wn1; Ws = Ws1; oh = w1h; ol = w1l; C = 128;
        } else if (idx < 65536) {
            wi = idx - 32768; Wn = Wn2; Ws = Ws2; oh = w2h; ol = w2l; C = 128;
        } else {
            wi = idx - 65536; Wn = Wn3; Ws = Ws3; oh = w3h; ol = w3l; C = 40;
        }
        int n = wi >> 7, k = wi & 127;
        float f = 0.f;
        if (n < C) f = Wn[k * C + n];
        else if (n < 2 * C) f = Ws[k * C + (n - C)];
        __nv_bfloat16 h = __float2bfloat16(f);
        oh[wi] = h;
        ol[wi] = __float2bfloat16(f - __bfloat162float(h));
    }
}

// ---------------- CSR chain ----------------
// count + record intra-row slot; g_cnt==0 at entry (reset by k_scan3 each run)
__global__ void k_count(const int* __restrict__ dst) {
    int e = blockIdx.x * blockDim.x + threadIdx.x;
    if (e < NE) g_eidx[e] = atomicAdd(&g_cnt[dst[e]], 1);
}
__global__ void k_scan1() {
    __shared__ int wsum[32];
    int i = blockIdx.x * 1024 + threadIdx.x;
    int lane = threadIdx.x & 31, wid = threadIdx.x >> 5;
    int v = (i < NN) ? g_cnt[i] : 0;
    int x = v;
#pragma unroll
    for (int o = 1; o < 32; o <<= 1) {
        int t = __shfl_up_sync(0xffffffffu, x, o);
        if (lane >= o) x += t;
    }
    if (lane == 31) wsum[wid] = x;
    __syncthreads();
    if (wid == 0) {
        int w = wsum[lane];
#pragma unroll
        for (int o = 1; o < 32; o <<= 1) {
            int t = __shfl_up_sync(0xffffffffu, w, o);
            if (lane >= o) w += t;
        }
        wsum[lane] = w;
    }
    __syncthreads();
    int off = wid ? wsum[wid - 1] : 0;
    int inc = x + off;
    if (i < NN) g_tscan[i] = inc;
    if (threadIdx.x == 1023) g_bsum[blockIdx.x] = inc;   // raw block total
}
__global__ void k_scan3() {
    __shared__ int pre;
    int t = threadIdx.x;
    int blk = (blockIdx.x * 256) >> 10;   // superblock index (constant per block)
    if (t == 0) pre = 0;
    __syncthreads();
    int contrib = (t < blk) ? g_bsum[t] : 0;   // blk <= 98 < 256
#pragma unroll
    for (int o = 16; o > 0; o >>= 1) contrib += __shfl_down_sync(0xffffffffu, contrib, o);
    if ((t & 31) == 0 && contrib) atomicAdd(&pre, contrib);
    __syncthreads();
    int i = blockIdx.x * 256 + t;
    if (i < NN) {
        g_rowptr[i + 1] = g_tscan[i] + pre;
        if (i == 0) g_rowptr[0] = 0;
        int d = g_cnt[i];
        g_invdeg[i] = 1.0f / (float)(d > 0 ? d : 1);
        g_cnt[i] = 0;   // restore replay invariant (fill no longer drains)
    }
}
// atomic-free fill: slot recorded during count
__global__ void k_fill(const int* __restrict__ src, const int* __restrict__ dst) {
    int e = blockIdx.x * blockDim.x + threadIdx.x;
    if (e < NE) {
        int p = g_rowptr[dst[e]] + g_eidx[e];
        g_esrc[p] = src[e];
    }
}

// ---------------- mma.sync bf16 dual GEMM ----------------
__device__ __forceinline__ void mma_bf16(float (&c)[4], const uint32_t (&a)[4],
                                         const uint32_t b0, const uint32_t b1) {
    asm volatile(
        "mma.sync.aligned.m16n8k16.row.col.f32.bf16.bf16.f32 "
        "{%0,%1,%2,%3}, {%4,%5,%6,%7}, {%8,%9}, {%0,%1,%2,%3};\n"
        : "+f"(c[0]), "+f"(c[1]), "+f"(c[2]), "+f"(c[3])
        : "r"(a[0]), "r"(a[1]), "r"(a[2]), "r"(a[3]), "r"(b0), "r"(b1));
}
__device__ __forceinline__ void ldsm_x4(uint32_t (&r)[4], uint32_t addr) {
    asm volatile("ldmatrix.sync.aligned.m8n8.x4.shared.b16 {%0,%1,%2,%3}, [%4];"
                 : "=r"(r[0]), "=r"(r[1]), "=r"(r[2]), "=r"(r[3]) : "r"(addr));
}

// SPLIT_IN=false: A pre-split (xh/xl bf16 pair, layer 1).
// SPLIT_IN=true : A is fp16 activations (xa); split to bf16 hi/lo during staging
//                 (fp16 -> bf16hi + residual-lo is exact: 11 = 8 + 3 mantissa bits).
template <bool SPLIT_IN>
__global__ __launch_bounds__(256, 2) void k_gemm_mma(
    const __nv_bfloat16* __restrict__ xh, const __nv_bfloat16* __restrict__ xl,
    const __half* __restrict__ xa,
    const __nv_bfloat16* __restrict__ wh, const __nv_bfloat16* __restrict__ wl,
    const float* __restrict__ bias, int C,
    __half* __restrict__ y, __half* __restrict__ s) {
    extern __shared__ __nv_bfloat16 smarr[];
    __nv_bfloat16* Ah = smarr;
    __nv_bfloat16* Al = Ah + 128 * KP;
    __nv_bfloat16* Bh = Al + 128 * KP;
    __nv_bfloat16* Bl = Bh + 64 * KP;

    int tid = threadIdx.x;
    int row0 = blockIdx.x * 128;
    int col0 = blockIdx.y * 64;

    for (int idx = tid; idx < 128 * 16; idx += 256) {
        int r = idx >> 4, k = (idx & 15) << 3;
        int grow = row0 + r;
        uint4 vh = make_uint4(0, 0, 0, 0), vl = vh;
        if (grow < NN) {
            if (SPLIT_IN) {
                uint4 va = *(const uint4*)(xa + grow * 128 + k);   // 8 halves
                uint32_t* pa = (uint32_t*)&va;
                uint32_t* ph = (uint32_t*)&vh;
                uint32_t* pl = (uint32_t*)&vl;
#pragma unroll
                for (int w = 0; w < 4; w++) {
                    float2 f = __half22float2(*(__half2*)&pa[w]);
                    __nv_bfloat16 h0 = __float2bfloat16(f.x), h1 = __float2bfloat16(f.y);
                    __nv_bfloat162 hp(h0, h1);
                    __nv_bfloat162 lp(__float2bfloat16(f.x - __bfloat162float(h0)),
                                      __float2bfloat16(f.y - __bfloat162float(h1)));
                    ph[w] = *(uint32_t*)&hp;
                    pl[w] = *(uint32_t*)&lp;
                }
            } else {
                vh = *(const uint4*)(xh + grow * 128 + k);
                vl = *(const uint4*)(xl + grow * 128 + k);
            }
        }
        *(uint4*)(Ah + r * KP + k) = vh;
        *(uint4*)(Al + r * KP + k) = vl;
    }
    for (int idx = tid; idx < 64 * 16; idx += 256) {
        int n = idx >> 4, k = (idx & 15) << 3;
        *(uint4*)(Bh + n * KP + k) = *(const uint4*)(wh + (col0 + n) * 128 + k);
        *(uint4*)(Bl + n * KP + k) = *(const uint4*)(wl + (col0 + n) * 128 + k);
    }
    __syncthreads();

    int wid = tid >> 5, lane = tid & 31;
    int mbase = (wid >> 1) * 32;
    int nbase = (wid & 1) * 32;
    int r4 = lane >> 2, tg = lane & 3;

    uint32_t aBase = smem_u32(Ah);
    uint32_t alBase = smem_u32(Al);
    uint32_t bBase = smem_u32(Bh);
    uint32_t blBase = smem_u32(Bl);

    int aRow = mbase + (lane & 15);
    int aOff = aRow * KP + ((lane >> 4) << 3);
    int q = lane >> 3;
    int bRow = nbase + ((q >> 1) << 3) + (lane & 7);
    int bOff = bRow * KP + ((q & 1) << 3);

    float acc[2][4][4];
#pragma unroll
    for (int mi = 0; mi < 2; mi++)
#pragma unroll
        for (int ni = 0; ni < 4; ni++)
#pragma unroll
            for (int c = 0; c < 4; c++) acc[mi][ni][c] = 0.f;

#pragma unroll
    for (int kc = 0; kc < 8; kc++) {
        int k0 = kc * 16;
        uint32_t ah[2][4], al[2][4];
        ldsm_x4(ah[0], aBase + (aOff + k0) * 2);
        ldsm_x4(ah[1], aBase + (aOff + 16 * KP + k0) * 2);
        ldsm_x4(al[0], alBase + (aOff + k0) * 2);
        ldsm_x4(al[1], alBase + (aOff + 16 * KP + k0) * 2);
        uint32_t bh01[4], bh23[4], bl01[4], bl23[4];
        ldsm_x4(bh01, bBase + (bOff + k0) * 2);
        ldsm_x4(bh23, bBase + (bOff + 16 * KP + k0) * 2);
        ldsm_x4(bl01, blBase + (bOff + k0) * 2);
        ldsm_x4(bl23, blBase + (bOff + 16 * KP + k0) * 2);
#pragma unroll
        for (int mi = 0; mi < 2; mi++) {
            mma_bf16(acc[mi][0], ah[mi], bh01[0], bh01[1]);
            mma_bf16(acc[mi][1], ah[mi], bh01[2], bh01[3]);
            mma_bf16(acc[mi][2], ah[mi], bh23[0], bh23[1]);
            mma_bf16(acc[mi][3], ah[mi], bh23[2], bh23[3]);
            mma_bf16(acc[mi][0], al[mi], bh01[0], bh01[1]);
            mma_bf16(acc[mi][1], al[mi], bh01[2], bh01[3]);
            mma_bf16(acc[mi][2], al[mi], bh23[0], bh23[1]);
            mma_bf16(acc[mi][3], al[mi], bh23[2], bh23[3]);
            mma_bf16(acc[mi][0], ah[mi], bl01[0], bl01[1]);
            mma_bf16(acc[mi][1], ah[mi], bl01[2], bl01[3]);
            mma_bf16(acc[mi][2], ah[mi], bl23[0], bl23[1]);
            mma_bf16(acc[mi][3], ah[mi], bl23[2], bl23[3]);
        }
    }

    // epilogue: y -> fp16, s -> fp16 (bias added in fp32)
#pragma unroll
    for (int mi = 0; mi < 2; mi++) {
#pragma unroll
        for (int ni = 0; ni < 4; ni++) {
            int grow0 = row0 + mbase + mi * 16 + r4;
            int cc = col0 + nbase + ni * 8 + tg * 2;
            if (cc >= 2 * C) continue;
#pragma unroll
            for (int half = 0; half < 2; half++) {
                int grow = grow0 + half * 8;
                if (grow >= NN) continue;
                float v0 = acc[mi][ni][half * 2 + 0];
                float v1 = acc[mi][ni][half * 2 + 1];
                if (cc < C) {
                    __half2 hv = __floats2half2_rn(v0, v1);
                    *(uint32_t*)(y + grow * C + cc) = *(uint32_t*)&hv;
                } else {
                    int c = cc - C;
                    __half2 hv = __floats2half2_rn(v0 + bias[c], v1 + bias[c + 1]);
                    *(uint32_t*)(s + grow * C + c) = *(uint32_t*)&hv;
                }
            }
        }
    }
}

// ---------------- gather (fp16 y) + finalize (F=128) -> fp16 activation ----------------
__global__ void k_aggfin128(const uint2* __restrict__ y2, const uint2* __restrict__ s2,
                            uint2* __restrict__ act2) {
    int n = (blockIdx.x * blockDim.x + threadIdx.x) >> 5;
    int lane = threadIdx.x & 31;
    if (n >= NN) return;
    int r0 = g_rowptr[n], r1 = g_rowptr[n + 1];
    float4 acc = make_float4(0.f, 0.f, 0.f, 0.f);
    for (int base = r0; base < r1; base += 32) {
        int idx = base + lane;
        int sid = (idx < r1) ? g_esrc[idx] : 0;
        int m = r1 - base;
        if (m > 32) m = 32;
#pragma unroll 4
        for (int j = 0; j < m; j++) {
            int sn = __shfl_sync(0xffffffffu, sid, j);
            uint2 v = y2[sn * 32 + lane];
            float2 p0 = __half22float2(*(__half2*)&v.x);
            float2 p1 = __half22float2(*(__half2*)&v.y);
            acc.x += p0.x; acc.y += p0.y; acc.z += p1.x; acc.w += p1.y;
        }
    }
    float id = g_invdeg[n];
    uint2 sv = s2[n * 32 + lane];
    float2 s01 = __half22float2(*(__half2*)&sv.x);
    float2 s23 = __half22float2(*(__half2*)&sv.y);
    float4 o;
    o.x = fmaxf(s01.x + acc.x * id, 0.f);
    o.y = fmaxf(s01.y + acc.y * id, 0.f);
    o.z = fmaxf(s23.x + acc.z * id, 0.f);
    o.w = fmaxf(s23.y + acc.w * id, 0.f);
    __half2 a01 = __floats2half2_rn(o.x, o.y);
    __half2 a23 = __floats2half2_rn(o.z, o.w);
    act2[n * 32 + lane] = make_uint2(*(uint32_t*)&a01, *(uint32_t*)&a23);
}

// ---------------- gather (fp16 y) + finalize (F=40) ----------------
__global__ void k_aggfin40(const uint32_t* __restrict__ y32, const uint32_t* __restrict__ s32,
                           float* __restrict__ out) {
    int n = (blockIdx.x * blockDim.x + threadIdx.x) >> 5;
    int lane = threadIdx.x & 31;
    if (n >= NN) return;
    int r0 = g_rowptr[n], r1 = g_rowptr[n + 1];
    float2 acc = make_float2(0.f, 0.f);
    for (int base = r0; base < r1; base += 32) {
        int idx = base + lane;
        int sid = (idx < r1) ? g_esrc[idx] : 0;
        int m = r1 - base;
        if (m > 32) m = 32;
#pragma unroll 4
        for (int j = 0; j < m; j++) {
            int sn = __shfl_sync(0xffffffffu, sid, j);
            if (lane < 20) {
                uint32_t v = y32[sn * 20 + lane];
                float2 p = __half22float2(*(__half2*)&v);
                acc.x += p.x; acc.y += p.y;
            }
        }
    }
    if (lane < 20) {
        float id = g_invdeg[n];
        uint32_t sv = s32[n * 20 + lane];
        float2 sp = __half22float2(*(__half2*)&sv);
        float2 o = make_float2(sp.x + acc.x * id, sp.y + acc.y * id);
        *(float2*)(out + n * 40 + lane * 2) = o;
    }
}

// ---------------- launch ----------------
extern "C" void kernel_launch(void* const* d_in, const int* in_sizes, int n_in,
                              void* d_out, int out_size) {
    const float* feat = (const float*)d_in[0];
    const int* src = (const int*)d_in[1];
    const int* dst = (const int*)d_in[2];
    const float* Ws1 = (const float*)d_in[3];
    const float* Wn1 = (const float*)d_in[4];
    const float* b1  = (const float*)d_in[5];
    const float* Ws2 = (const float*)d_in[6];
    const float* Wn2 = (const float*)d_in[7];
    const float* b2  = (const float*)d_in[8];
    const float* Ws3 = (const float*)d_in[9];
    const float* Wn3 = (const float*)d_in[10];
    const float* b3  = (const float*)d_in[11];
    float* out = (float*)d_out;

    __half *py, *ps, *pa;
    __nv_bfloat16 *pxh, *pxl, *pw1h, *pw1l, *pw2h, *pw2l, *pw3h, *pw3l;
    cudaGetSymbolAddress((void**)&py, g_y);
    cudaGetSymbolAddress((void**)&ps, g_s);
    cudaGetSymbolAddress((void**)&pa, g_act);
    cudaGetSymbolAddress((void**)&pxh, g_xh);
    cudaGetSymbolAddress((void**)&pxl, g_xl);
    cudaGetSymbolAddress((void**)&pw1h, g_w1h);
    cudaGetSymbolAddress((void**)&pw1l, g_w1l);
    cudaGetSymbolAddress((void**)&pw2h, g_w2h);
    cudaGetSymbolAddress((void**)&pw2l, g_w2l);
    cudaGetSymbolAddress((void**)&pw3h, g_w3h);
    cudaGetSymbolAddress((void**)&pw3l, g_w3l);

    const int SMEM = (128 + 128 + 64 + 64) * KP * 2;  // 104448
    cudaFuncSetAttribute(k_gemm_mma<false>, cudaFuncAttributeMaxDynamicSharedMemorySize, SMEM);
    cudaFuncSetAttribute(k_gemm_mma<true>,  cudaFuncAttributeMaxDynamicSharedMemorySize, SMEM);

    int nbE = (NE + 255) / 256;
    int nbScan = (NN + 1023) / 1024;
    int gRows = (NN + 127) / 128;   // 782
    int gAgg = (NN + 7) / 8;

    // side stream for CSR chain
    cudaStream_t s1;
    cudaStreamCreate(&s1);
    cudaEvent_t e0, e1;
    cudaEventCreateWithFlags(&e0, cudaEventDisableTiming);
    cudaEventCreateWithFlags(&e1, cudaEventDisableTiming);

    cudaEventRecord(e0, 0);
    cudaStreamWaitEvent(s1, e0, 0);

    k_count<<<nbE, 256, 0, s1>>>(dst);
    k_scan1<<<nbScan, 1024, 0, s1>>>();
    k_scan3<<<(NN + 255) / 256, 256, 0, s1>>>();
    k_fill<<<nbE, 256, 0, s1>>>(src, dst);
    cudaEventRecord(e1, s1);

    // main stream: feature/weight split + layer-1 GEMM
    k_split<<<(NN * 32 + 255) / 256, 256>>>(
        (const float4*)feat, (uint2*)pxh, (uint2*)pxl,
        Wn1, Ws1, Wn2, Ws2, Wn3, Ws3,
        pw1h, pw1l, pw2h, pw2l, pw3h, pw3l);
    k_gemm_mma<false><<<dim3(gRows, 4), 256, SMEM>>>(pxh, pxl, nullptr,
                                                     pw1h, pw1l, b1, 128, py, ps);

    cudaStreamWaitEvent(0, e1, 0);

    k_aggfin128<<<gAgg, 256>>>((const uint2*)py, (const uint2*)ps, (uint2*)pa);
    // layer 2 (fp16 activations, in-staging split)
    k_gemm_mma<true><<<dim3(gRows, 4), 256, SMEM>>>(nullptr, nullptr, pa,
                                                    pw2h, pw2l, b2, 128, py, ps);
    k_aggfin128<<<gAgg, 256>>>((const uint2*)py, (const uint2*)ps, (uint2*)pa);
    // layer 3
    k_gemm_mma<true><<<dim3(gRows, 2), 256, SMEM>>>(nullptr, nullptr, pa,
                                                    pw3h, pw3l, b3, 40, py, ps);
    k_aggfin40<<<gAgg, 256>>>((const uint32_t*)py, (const uint32_t*)ps, out);
}

// round 16
// speedup vs baseline: 1.6395x; 1.1364x over previous
#include <cuda_runtime.h>
#include <cuda_bf16.h>
#include <cuda_fp16.h>
#include <cstdint>

#define NN 100000
#define NE 1600000
#define KP 136   // padded K stride (16-bit elems): row stride 68 words -> ldmatrix conflict-free

// ---------------- device scratch ----------------
__device__ __half g_y[NN * 128];     // neighbor projection, fp16
__device__ __half g_s[NN * 128];     // self projection + bias, fp16
__device__ __half g_act[NN * 128];   // inter-layer activation, fp16
__device__ __nv_bfloat16 g_xh[NN * 128];   // layer-1 input split (from fp32 features)
__device__ __nv_bfloat16 g_xl[NN * 128];
__device__ __nv_bfloat16 g_w1h[256 * 128], g_w1l[256 * 128];   // layer-1 weights (bf16 pair)
__device__ __half g_w2h[256 * 128], g_w2l[256 * 128];          // layer-2 weights (fp16 pair)
__device__ __half g_w3h[128 * 128], g_w3l[128 * 128];          // layer-3 weights (fp16 pair)
__device__ float g_invdeg[NN];
__device__ int   g_rowptr[NN + 1];
__device__ int   g_cnt[NN];          // zero at entry of every run (reset in k_scan3)
__device__ int   g_eidx[NE];         // per-edge intra-row slot (recorded during count)
__device__ int   g_tscan[NN];
__device__ int   g_bsum[128];
__device__ int   g_esrc[NE];

__device__ __forceinline__ uint32_t smem_u32(const void* p) {
    uint32_t a;
    asm("{ .reg .u64 t; cvta.to.shared.u64 t, %1; cvt.u32.u64 %0, t; }" : "=r"(a) : "l"(p));
    return a;
}

// ---------------- front: weight split + feature split ----------------
__global__ void k_split(const float4* __restrict__ x4, uint2* __restrict__ xh2,
                        uint2* __restrict__ xl2,
                        const float* __restrict__ Wn1, const float* __restrict__ Ws1,
                        const float* __restrict__ Wn2, const float* __restrict__ Ws2,
                        const float* __restrict__ Wn3, const float* __restrict__ Ws3,
                        __nv_bfloat16* __restrict__ w1h, __nv_bfloat16* __restrict__ w1l,
                        __half* __restrict__ w2h, __half* __restrict__ w2l,
                        __half* __restrict__ w3h, __half* __restrict__ w3l) {
    int idx = blockIdx.x * blockDim.x + threadIdx.x;
    if (idx < NN * 32) {
        float4 v = x4[idx];
        __nv_bfloat16 hx = __float2bfloat16(v.x), hy = __float2bfloat16(v.y);
        __nv_bfloat16 hz = __float2bfloat16(v.z), hw = __float2bfloat16(v.w);
        __nv_bfloat162 h01(hx, hy), h23(hz, hw);
        __nv_bfloat162 l01(__float2bfloat16(v.x - __bfloat162float(hx)),
                           __float2bfloat16(v.y - __bfloat162float(hy)));
        __nv_bfloat162 l23(__float2bfloat16(v.z - __bfloat162float(hz)),
                           __float2bfloat16(v.w - __bfloat162float(hw)));
        xh2[idx] = make_uint2(*(uint32_t*)&h01, *(uint32_t*)&h23);
        xl2[idx] = make_uint2(*(uint32_t*)&l01, *(uint32_t*)&l23);
    }
    if (idx < 81920) {
        if (idx < 32768) {
            // layer-1 weights: bf16 hi/lo
            int wi = idx;
            int n = wi >> 7, k = wi & 127;
            float f = (n < 128) ? Wn1[k * 128 + n] : Ws1[k * 128 + (n - 128)];
            __nv_bfloat16 h = __float2bfloat16(f);
            w1h[wi] = h;
            w1l[wi] = __float2bfloat16(f - __bfloat162float(h));
        } else {
            // layer-2/3 weights: fp16 hi/lo
            const float* Wn;
            const float* Ws;
            __half *oh, *ol;
            int wi, C;
            if (idx < 65536) {
                wi = idx - 32768; Wn = Wn2; Ws = Ws2; oh = w2h; ol = w2l; C = 128;
            } else {
                wi = idx - 65536; Wn = Wn3; Ws = Ws3; oh = w3h; ol = w3l; C = 40;
            }
            int n = wi >> 7, k = wi & 127;
            float f = 0.f;
            if (n < C) f = Wn[k * C + n];
            else if (n < 2 * C) f = Ws[k * C + (n - C)];
            __half h = __float2half(f);
            oh[wi] = h;
            ol[wi] = __float2half(f - __half2float(h));
        }
    }
}

// ---------------- CSR chain ----------------
__global__ void k_count(const int* __restrict__ dst) {
    int e = blockIdx.x * blockDim.x + threadIdx.x;
    if (e < NE) g_eidx[e] = atomicAdd(&g_cnt[dst[e]], 1);
}
__global__ void k_scan1() {
    __shared__ int wsum[32];
    int i = blockIdx.x * 1024 + threadIdx.x;
    int lane = threadIdx.x & 31, wid = threadIdx.x >> 5;
    int v = (i < NN) ? g_cnt[i] : 0;
    int x = v;
#pragma unroll
    for (int o = 1; o < 32; o <<= 1) {
        int t = __shfl_up_sync(0xffffffffu, x, o);
        if (lane >= o) x += t;
    }
    if (lane == 31) wsum[wid] = x;
    __syncthreads();
    if (wid == 0) {
        int w = wsum[lane];
#pragma unroll
        for (int o = 1; o < 32; o <<= 1) {
            int t = __shfl_up_sync(0xffffffffu, w, o);
            if (lane >= o) w += t;
        }
        wsum[lane] = w;
    }
    __syncthreads();
    int off = wid ? wsum[wid - 1] : 0;
    int inc = x + off;
    if (i < NN) g_tscan[i] = inc;
    if (threadIdx.x == 1023) g_bsum[blockIdx.x] = inc;   // raw block total
}
__global__ void k_scan3() {
    __shared__ int pre;
    int t = threadIdx.x;
    int blk = (blockIdx.x * 256) >> 10;   // superblock index (constant per block)
    if (t == 0) pre = 0;
    __syncthreads();
    int contrib = (t < blk) ? g_bsum[t] : 0;   // blk <= 98 < 256
#pragma unroll
    for (int o = 16; o > 0; o >>= 1) contrib += __shfl_down_sync(0xffffffffu, contrib, o);
    if ((t & 31) == 0 && contrib) atomicAdd(&pre, contrib);
    __syncthreads();
    int i = blockIdx.x * 256 + t;
    if (i < NN) {
        g_rowptr[i + 1] = g_tscan[i] + pre;
        if (i == 0) g_rowptr[0] = 0;
        int d = g_cnt[i];
        g_invdeg[i] = 1.0f / (float)(d > 0 ? d : 1);
        g_cnt[i] = 0;   // restore replay invariant
    }
}
__global__ void k_fill(const int* __restrict__ src, const int* __restrict__ dst) {
    int e = blockIdx.x * blockDim.x + threadIdx.x;
    if (e < NE) {
        int p = g_rowptr[dst[e]] + g_eidx[e];
        g_esrc[p] = src[e];
    }
}

// ---------------- MMA helpers ----------------
__device__ __forceinline__ void mma_bf16(float (&c)[4], const uint32_t (&a)[4],
                                         const uint32_t b0, const uint32_t b1) {
    asm volatile(
        "mma.sync.aligned.m16n8k16.row.col.f32.bf16.bf16.f32 "
        "{%0,%1,%2,%3}, {%4,%5,%6,%7}, {%8,%9}, {%0,%1,%2,%3};\n"
        : "+f"(c[0]), "+f"(c[1]), "+f"(c[2]), "+f"(c[3])
        : "r"(a[0]), "r"(a[1]), "r"(a[2]), "r"(a[3]), "r"(b0), "r"(b1));
}
__device__ __forceinline__ void mma_f16(float (&c)[4], const uint32_t (&a)[4],
                                        const uint32_t b0, const uint32_t b1) {
    asm volatile(
        "mma.sync.aligned.m16n8k16.row.col.f32.f16.f16.f32 "
        "{%0,%1,%2,%3}, {%4,%5,%6,%7}, {%8,%9}, {%0,%1,%2,%3};\n"
        : "+f"(c[0]), "+f"(c[1]), "+f"(c[2]), "+f"(c[3])
        : "r"(a[0]), "r"(a[1]), "r"(a[2]), "r"(a[3]), "r"(b0), "r"(b1));
}
__device__ __forceinline__ void ldsm_x4(uint32_t (&r)[4], uint32_t addr) {
    asm volatile("ldmatrix.sync.aligned.m8n8.x4.shared.b16 {%0,%1,%2,%3}, [%4];"
                 : "=r"(r[0]), "=r"(r[1]), "=r"(r[2]), "=r"(r[3]) : "r"(addr));
}

// ---------------- layer-1 GEMM: bf16 3-term (A = pre-split features), occ-2 ----------------
__global__ __launch_bounds__(256, 2) void k_gemm_l1(
    const __nv_bfloat16* __restrict__ xh, const __nv_bfloat16* __restrict__ xl,
    const __nv_bfloat16* __restrict__ wh, const __nv_bfloat16* __restrict__ wl,
    const float* __restrict__ bias,
    __half* __restrict__ y, __half* __restrict__ s) {
    extern __shared__ __nv_bfloat16 smarr[];
    __nv_bfloat16* Ah = smarr;
    __nv_bfloat16* Al = Ah + 128 * KP;
    __nv_bfloat16* Bh = Al + 128 * KP;
    __nv_bfloat16* Bl = Bh + 64 * KP;

    int tid = threadIdx.x;
    int row0 = blockIdx.x * 128;
    int col0 = blockIdx.y * 64;
    const int C = 128;

    for (int idx = tid; idx < 128 * 16; idx += 256) {
        int r = idx >> 4, k = (idx & 15) << 3;
        int grow = row0 + r;
        uint4 vh = make_uint4(0, 0, 0, 0), vl = vh;
        if (grow < NN) {
            vh = *(const uint4*)(xh + grow * 128 + k);
            vl = *(const uint4*)(xl + grow * 128 + k);
        }
        *(uint4*)(Ah + r * KP + k) = vh;
        *(uint4*)(Al + r * KP + k) = vl;
    }
    for (int idx = tid; idx < 64 * 16; idx += 256) {
        int n = idx >> 4, k = (idx & 15) << 3;
        *(uint4*)(Bh + n * KP + k) = *(const uint4*)(wh + (col0 + n) * 128 + k);
        *(uint4*)(Bl + n * KP + k) = *(const uint4*)(wl + (col0 + n) * 128 + k);
    }
    __syncthreads();

    int wid = tid >> 5, lane = tid & 31;
    int mbase = (wid >> 1) * 32;
    int nbase = (wid & 1) * 32;
    int r4 = lane >> 2, tg = lane & 3;

    uint32_t aBase = smem_u32(Ah);
    uint32_t alBase = smem_u32(Al);
    uint32_t bBase = smem_u32(Bh);
    uint32_t blBase = smem_u32(Bl);

    int aRow = mbase + (lane & 15);
    int aOff = aRow * KP + ((lane >> 4) << 3);
    int q = lane >> 3;
    int bRow = nbase + ((q >> 1) << 3) + (lane & 7);
    int bOff = bRow * KP + ((q & 1) << 3);

    float acc[2][4][4];
#pragma unroll
    for (int mi = 0; mi < 2; mi++)
#pragma unroll
        for (int ni = 0; ni < 4; ni++)
#pragma unroll
            for (int c = 0; c < 4; c++) acc[mi][ni][c] = 0.f;

#pragma unroll
    for (int kc = 0; kc < 8; kc++) {
        int k0 = kc * 16;
        uint32_t ah[2][4], al[2][4];
        ldsm_x4(ah[0], aBase + (aOff + k0) * 2);
        ldsm_x4(ah[1], aBase + (aOff + 16 * KP + k0) * 2);
        ldsm_x4(al[0], alBase + (aOff + k0) * 2);
        ldsm_x4(al[1], alBase + (aOff + 16 * KP + k0) * 2);
        uint32_t bh01[4], bh23[4], bl01[4], bl23[4];
        ldsm_x4(bh01, bBase + (bOff + k0) * 2);
        ldsm_x4(bh23, bBase + (bOff + 16 * KP + k0) * 2);
        ldsm_x4(bl01, blBase + (bOff + k0) * 2);
        ldsm_x4(bl23, blBase + (bOff + 16 * KP + k0) * 2);
#pragma unroll
        for (int mi = 0; mi < 2; mi++) {
            mma_bf16(acc[mi][0], ah[mi], bh01[0], bh01[1]);
            mma_bf16(acc[mi][1], ah[mi], bh01[2], bh01[3]);
            mma_bf16(acc[mi][2], ah[mi], bh23[0], bh23[1]);
            mma_bf16(acc[mi][3], ah[mi], bh23[2], bh23[3]);
            mma_bf16(acc[mi][0], al[mi], bh01[0], bh01[1]);
            mma_bf16(acc[mi][1], al[mi], bh01[2], bh01[3]);
            mma_bf16(acc[mi][2], al[mi], bh23[0], bh23[1]);
            mma_bf16(acc[mi][3], al[mi], bh23[2], bh23[3]);
            mma_bf16(acc[mi][0], ah[mi], bl01[0], bl01[1]);
            mma_bf16(acc[mi][1], ah[mi], bl01[2], bl01[3]);
            mma_bf16(acc[mi][2], ah[mi], bl23[0], bl23[1]);
            mma_bf16(acc[mi][3], ah[mi], bl23[2], bl23[3]);
        }
    }

#pragma unroll
    for (int mi = 0; mi < 2; mi++) {
#pragma unroll
        for (int ni = 0; ni < 4; ni++) {
            int grow0 = row0 + mbase + mi * 16 + r4;
            int cc = col0 + nbase + ni * 8 + tg * 2;
#pragma unroll
            for (int half = 0; half < 2; half++) {
                int grow = grow0 + half * 8;
                if (grow >= NN) continue;
                float v0 = acc[mi][ni][half * 2 + 0];
                float v1 = acc[mi][ni][half * 2 + 1];
                if (cc < C) {
                    __half2 hv = __floats2half2_rn(v0, v1);
                    *(uint32_t*)(y + grow * C + cc) = *(uint32_t*)&hv;
                } else {
                    int c = cc - C;
                    __half2 hv = __floats2half2_rn(v0 + bias[c], v1 + bias[c + 1]);
                    *(uint32_t*)(s + grow * C + c) = *(uint32_t*)&hv;
                }
            }
        }
    }
}

// ---------------- layer-2/3 GEMM: fp16 2-term (A exact fp16, W = hi+lo), occ-3 ----------------
__global__ __launch_bounds__(256, 3) void k_gemm_f16(
    const __half* __restrict__ xa,
    const __half* __restrict__ wh, const __half* __restrict__ wl,
    const float* __restrict__ bias, int C,
    __half* __restrict__ y, __half* __restrict__ s) {
    extern __shared__ __half smf[];
    __half* As = smf;                 // [128][KP]
    __half* Bh = As + 128 * KP;       // [64][KP]
    __half* Bl = Bh + 64 * KP;

    int tid = threadIdx.x;
    int row0 = blockIdx.x * 128;
    int col0 = blockIdx.y * 64;

    // stage A (raw fp16 copy — exact, no split needed)
    for (int idx = tid; idx < 128 * 16; idx += 256) {
        int r = idx >> 4, k = (idx & 15) << 3;
        int grow = row0 + r;
        uint4 v = make_uint4(0, 0, 0, 0);
        if (grow < NN) v = *(const uint4*)(xa + grow * 128 + k);
        *(uint4*)(As + r * KP + k) = v;
    }
    for (int idx = tid; idx < 64 * 16; idx += 256) {
        int n = idx >> 4, k = (idx & 15) << 3;
        *(uint4*)(Bh + n * KP + k) = *(const uint4*)(wh + (col0 + n) * 128 + k);
        *(uint4*)(Bl + n * KP + k) = *(const uint4*)(wl + (col0 + n) * 128 + k);
    }
    __syncthreads();

    int wid = tid >> 5, lane = tid & 31;
    int mbase = (wid >> 1) * 32;
    int nbase = (wid & 1) * 32;
    int r4 = lane >> 2, tg = lane & 3;

    uint32_t aBase = smem_u32(As);
    uint32_t bBase = smem_u32(Bh);
    uint32_t blBase = smem_u32(Bl);

    int aRow = mbase + (lane & 15);
    int aOff = aRow * KP + ((lane >> 4) << 3);
    int q = lane >> 3;
    int bRow = nbase + ((q >> 1) << 3) + (lane & 7);
    int bOff = bRow * KP + ((q & 1) << 3);

    float acc[2][4][4];
#pragma unroll
    for (int mi = 0; mi < 2; mi++)
#pragma unroll
        for (int ni = 0; ni < 4; ni++)
#pragma unroll
            for (int c = 0; c < 4; c++) acc[mi][ni][c] = 0.f;

#pragma unroll
    for (int kc = 0; kc < 8; kc++) {
        int k0 = kc * 16;
        uint32_t a[2][4];
        ldsm_x4(a[0], aBase + (aOff + k0) * 2);
        ldsm_x4(a[1], aBase + (aOff + 16 * KP + k0) * 2);
        uint32_t bh01[4], bh23[4], bl01[4], bl23[4];
        ldsm_x4(bh01, bBase + (bOff + k0) * 2);
        ldsm_x4(bh23, bBase + (bOff + 16 * KP + k0) * 2);
        ldsm_x4(bl01, blBase + (bOff + k0) * 2);
        ldsm_x4(bl23, blBase + (bOff + 16 * KP + k0) * 2);
#pragma unroll
        for (int mi = 0; mi < 2; mi++) {
            mma_f16(acc[mi][0], a[mi], bh01[0], bh01[1]);
            mma_f16(acc[mi][1], a[mi], bh01[2], bh01[3]);
            mma_f16(acc[mi][2], a[mi], bh23[0], bh23[1]);
            mma_f16(acc[mi][3], a[mi], bh23[2], bh23[3]);
            mma_f16(acc[mi][0], a[mi], bl01[0], bl01[1]);
            mma_f16(acc[mi][1], a[mi], bl01[2], bl01[3]);
            mma_f16(acc[mi][2], a[mi], bl23[0], bl23[1]);
            mma_f16(acc[mi][3], a[mi], bl23[2], bl23[3]);
        }
    }

#pragma unroll
    for (int mi = 0; mi < 2; mi++) {
#pragma unroll
        for (int ni = 0; ni < 4; ni++) {
            int grow0 = row0 + mbase + mi * 16 + r4;
            int cc = col0 + nbase + ni * 8 + tg * 2;
            if (cc >= 2 * C) continue;
#pragma unroll
            for (int half = 0; half < 2; half++) {
                int grow = grow0 + half * 8;
                if (grow >= NN) continue;
                float v0 = acc[mi][ni][half * 2 + 0];
                float v1 = acc[mi][ni][half * 2 + 1];
                if (cc < C) {
                    __half2 hv = __floats2half2_rn(v0, v1);
                    *(uint32_t*)(y + grow * C + cc) = *(uint32_t*)&hv;
                } else {
                    int c = cc - C;
                    __half2 hv = __floats2half2_rn(v0 + bias[c], v1 + bias[c + 1]);
                    *(uint32_t*)(s + grow * C + c) = *(uint32_t*)&hv;
                }
            }
        }
    }
}

// ---------------- gather (fp16 y) + finalize (F=128) -> fp16 activation ----------------
__global__ void k_aggfin128(const uint2* __restrict__ y2, const uint2* __restrict__ s2,
                            uint2* __restrict__ act2) {
    int n = (blockIdx.x * blockDim.x + threadIdx.x) >> 5;
    int lane = threadIdx.x & 31;
    if (n >= NN) return;
    int r0 = g_rowptr[n], r1 = g_rowptr[n + 1];
    float4 acc = make_float4(0.f, 0.f, 0.f, 0.f);
    for (int base = r0; base < r1; base += 32) {
        int idx = base + lane;
        int sid = (idx < r1) ? g_esrc[idx] : 0;
        int m = r1 - base;
        if (m > 32) m = 32;
#pragma unroll 4
        for (int j = 0; j < m; j++) {
            int sn = __shfl_sync(0xffffffffu, sid, j);
            uint2 v = y2[sn * 32 + lane];
            float2 p0 = __half22float2(*(__half2*)&v.x);
            float2 p1 = __half22float2(*(__half2*)&v.y);
            acc.x += p0.x; acc.y += p0.y; acc.z += p1.x; acc.w += p1.y;
        }
    }
    float id = g_invdeg[n];
    uint2 sv = s2[n * 32 + lane];
    float2 s01 = __half22float2(*(__half2*)&sv.x);
    float2 s23 = __half22float2(*(__half2*)&sv.y);
    float4 o;
    o.x = fmaxf(s01.x + acc.x * id, 0.f);
    o.y = fmaxf(s01.y + acc.y * id, 0.f);
    o.z = fmaxf(s23.x + acc.z * id, 0.f);
    o.w = fmaxf(s23.y + acc.w * id, 0.f);
    __half2 a01 = __floats2half2_rn(o.x, o.y);
    __half2 a23 = __floats2half2_rn(o.z, o.w);
    act2[n * 32 + lane] = make_uint2(*(uint32_t*)&a01, *(uint32_t*)&a23);
}

// ---------------- gather (fp16 y) + finalize (F=40) ----------------
__global__ void k_aggfin40(const uint32_t* __restrict__ y32, const uint32_t* __restrict__ s32,
                           float* __restrict__ out) {
    int n = (blockIdx.x * blockDim.x + threadIdx.x) >> 5;
    int lane = threadIdx.x & 31;
    if (n >= NN) return;
    int r0 = g_rowptr[n], r1 = g_rowptr[n + 1];
    float2 acc = make_float2(0.f, 0.f);
    for (int base = r0; base < r1; base += 32) {
        int idx = base + lane;
        int sid = (idx < r1) ? g_esrc[idx] : 0;
        int m = r1 - base;
        if (m > 32) m = 32;
#pragma unroll 4
        for (int j = 0; j < m; j++) {
            int sn = __shfl_sync(0xffffffffu, sid, j);
            if (lane < 20) {
                uint32_t v = y32[sn * 20 + lane];
                float2 p = __half22float2(*(__half2*)&v);
                acc.x += p.x; acc.y += p.y;
            }
        }
    }
    if (lane < 20) {
        float id = g_invdeg[n];
        uint32_t sv = s32[n * 20 + lane];
        float2 sp = __half22float2(*(__half2*)&sv);
        float2 o = make_float2(sp.x + acc.x * id, sp.y + acc.y * id);
        *(float2*)(out + n * 40 + lane * 2) = o;
    }
}

// ---------------- launch ----------------
extern "C" void kernel_launch(void* const* d_in, const int* in_sizes, int n_in,
                              void* d_out, int out_size) {
    const float* feat = (const float*)d_in[0];
    const int* src = (const int*)d_in[1];
    const int* dst = (const int*)d_in[2];
    const float* Ws1 = (const float*)d_in[3];
    const float* Wn1 = (const float*)d_in[4];
    const float* b1  = (const float*)d_in[5];
    const float* Ws2 = (const float*)d_in[6];
    const float* Wn2 = (const float*)d_in[7];
    const float* b2  = (const float*)d_in[8];
    const float* Ws3 = (const float*)d_in[9];
    const float* Wn3 = (const float*)d_in[10];
    const float* b3  = (const float*)d_in[11];
    float* out = (float*)d_out;

    __half *py, *ps, *pa, *pw2h, *pw2l, *pw3h, *pw3l;
    __nv_bfloat16 *pxh, *pxl, *pw1h, *pw1l;
    cudaGetSymbolAddress((void**)&py, g_y);
    cudaGetSymbolAddress((void**)&ps, g_s);
    cudaGetSymbolAddress((void**)&pa, g_act);
    cudaGetSymbolAddress((void**)&pxh, g_xh);
    cudaGetSymbolAddress((void**)&pxl, g_xl);
    cudaGetSymbolAddress((void**)&pw1h, g_w1h);
    cudaGetSymbolAddress((void**)&pw1l, g_w1l);
    cudaGetSymbolAddress((void**)&pw2h, g_w2h);
    cudaGetSymbolAddress((void**)&pw2l, g_w2l);
    cudaGetSymbolAddress((void**)&pw3h, g_w3h);
    cudaGetSymbolAddress((void**)&pw3l, g_w3l);

    const int SMEM_L1 = (128 + 128 + 64 + 64) * KP * 2;  // 104448
    const int SMEM_F16 = (128 + 64 + 64) * KP * 2;       // 69632
    cudaFuncSetAttribute(k_gemm_l1, cudaFuncAttributeMaxDynamicSharedMemorySize, SMEM_L1);
    cudaFuncSetAttribute(k_gemm_f16, cudaFuncAttributeMaxDynamicSharedMemorySize, SMEM_F16);

    int nbE = (NE + 255) / 256;
    int nbScan = (NN + 1023) / 1024;
    int gRows = (NN + 127) / 128;   // 782
    int gAgg = (NN + 7) / 8;

    // side stream for CSR chain
    cudaStream_t s1;
    cudaStreamCreate(&s1);
    cudaEvent_t e0, e1;
    cudaEventCreateWithFlags(&e0, cudaEventDisableTiming);
    cudaEventCreateWithFlags(&e1, cudaEventDisableTiming);

    cudaEventRecord(e0, 0);
    cudaStreamWaitEvent(s1, e0, 0);

    k_count<<<nbE, 256, 0, s1>>>(dst);
    k_scan1<<<nbScan, 1024, 0, s1>>>();
    k_scan3<<<(NN + 255) / 256, 256, 0, s1>>>();
    k_fill<<<nbE, 256, 0, s1>>>(src, dst);
    cudaEventRecord(e1, s1);

    // main stream: feature/weight split + layer-1 GEMM (bf16 3-term)
    k_split<<<(NN * 32 + 255) / 256, 256>>>(
        (const float4*)feat, (uint2*)pxh, (uint2*)pxl,
        Wn1, Ws1, Wn2, Ws2, Wn3, Ws3,
        pw1h, pw1l, pw2h, pw2l, pw3h, pw3l);
    k_gemm_l1<<<dim3(gRows, 4), 256, SMEM_L1>>>(pxh, pxl, pw1h, pw1l, b1, py, ps);

    cudaStreamWaitEvent(0, e1, 0);

    k_aggfin128<<<gAgg, 256>>>((const uint2*)py, (const uint2*)ps, (uint2*)pa);
    // layer 2 (fp16 2-term)
    k_gemm_f16<<<dim3(gRows, 4), 256, SMEM_F16>>>(pa, pw2h, pw2l, b2, 128, py, ps);
    k_aggfin128<<<gAgg, 256>>>((const uint2*)py, (const uint2*)ps, (uint2*)pa);
    // layer 3 (fp16 2-term)
    k_gemm_f16<<<dim3(gRows, 2), 256, SMEM_F16>>>(pa, pw3h, pw3l, b3, 40, py, ps);
    k_aggfin40<<<gAgg, 256>>>((const uint32_t*)py, (const uint32_t*)ps, out);
}

// round 17
// speedup vs baseline: 1.8310x; 1.1168x over previous
#include <cuda_runtime.h>
#include <cuda_bf16.h>
#include <cuda_fp16.h>
#include <cstdint>

#define NN 100000
#define NE 1600000
#define KP 136   // padded K stride (16-bit elems): row stride 68 words -> ldmatrix conflict-free

// ---------------- device scratch ----------------
__device__ __half g_y[NN * 128];     // neighbor projection, fp16
__device__ __half g_s[NN * 128];     // self projection + bias, fp16
__device__ __half g_act[NN * 128];   // fp16 features (layer 1) / inter-layer activation
__device__ __half g_w1h[256 * 128], g_w1l[256 * 128];   // all weights: fp16 hi/lo pairs
__device__ __half g_w2h[256 * 128], g_w2l[256 * 128];
__device__ __half g_w3h[128 * 128], g_w3l[128 * 128];
__device__ float g_invdeg[NN];
__device__ int   g_rowptr[NN + 1];
__device__ int   g_cnt[NN];          // zero at entry of every run (reset in k_scan3)
__device__ int   g_eidx[NE];         // per-edge intra-row slot (recorded during count)
__device__ int   g_tscan[NN];
__device__ int   g_bsum[128];
__device__ int   g_esrc[NE];

__device__ __forceinline__ uint32_t smem_u32(const void* p) {
    uint32_t a;
    asm("{ .reg .u64 t; cvta.to.shared.u64 t, %1; cvt.u32.u64 %0, t; }" : "=r"(a) : "l"(p));
    return a;
}

// ---------------- front: features -> fp16, all weights -> fp16 hi/lo ----------------
__global__ void k_split(const float4* __restrict__ x4, uint2* __restrict__ act2,
                        const float* __restrict__ Wn1, const float* __restrict__ Ws1,
                        const float* __restrict__ Wn2, const float* __restrict__ Ws2,
                        const float* __restrict__ Wn3, const float* __restrict__ Ws3,
                        __half* __restrict__ w1h, __half* __restrict__ w1l,
                        __half* __restrict__ w2h, __half* __restrict__ w2l,
                        __half* __restrict__ w3h, __half* __restrict__ w3l) {
    int idx = blockIdx.x * blockDim.x + threadIdx.x;
    if (idx < NN * 32) {
        float4 v = x4[idx];
        __half2 h01 = __floats2half2_rn(v.x, v.y);
        __half2 h23 = __floats2half2_rn(v.z, v.w);
        act2[idx] = make_uint2(*(uint32_t*)&h01, *(uint32_t*)&h23);
    }
    if (idx < 81920) {
        const float* Wn;
        const float* Ws;
        __half *oh, *ol;
        int wi, C;
        if (idx < 32768) {
            wi = idx; Wn = Wn1; Ws = Ws1; oh = w1h; ol = w1l; C = 128;
        } else if (idx < 65536) {
            wi = idx - 32768; Wn = Wn2; Ws = Ws2; oh = w2h; ol = w2l; C = 128;
        } else {
            wi = idx - 65536; Wn = Wn3; Ws = Ws3; oh = w3h; ol = w3l; C = 40;
        }
        int n = wi >> 7, k = wi & 127;
        float f = 0.f;
        if (n < C) f = Wn[k * C + n];
        else if (n < 2 * C) f = Ws[k * C + (n - C)];
        __half h = __float2half(f);
        oh[wi] = h;
        ol[wi] = __float2half(f - __half2float(h));
    }
}

// ---------------- CSR chain ----------------
__global__ void k_count(const int* __restrict__ dst) {
    int e = blockIdx.x * blockDim.x + threadIdx.x;
    if (e < NE) g_eidx[e] = atomicAdd(&g_cnt[dst[e]], 1);
}
__global__ void k_scan1() {
    __shared__ int wsum[32];
    int i = blockIdx.x * 1024 + threadIdx.x;
    int lane = threadIdx.x & 31, wid = threadIdx.x >> 5;
    int v = (i < NN) ? g_cnt[i] : 0;
    int x = v;
#pragma unroll
    for (int o = 1; o < 32; o <<= 1) {
        int t = __shfl_up_sync(0xffffffffu, x, o);
        if (lane >= o) x += t;
    }
    if (lane == 31) wsum[wid] = x;
    __syncthreads();
    if (wid == 0) {
        int w = wsum[lane];
#pragma unroll
        for (int o = 1; o < 32; o <<= 1) {
            int t = __shfl_up_sync(0xffffffffu, w, o);
            if (lane >= o) w += t;
        }
        wsum[lane] = w;
    }
    __syncthreads();
    int off = wid ? wsum[wid - 1] : 0;
    int inc = x + off;
    if (i < NN) g_tscan[i] = inc;
    if (threadIdx.x == 1023) g_bsum[blockIdx.x] = inc;   // raw block total
}
__global__ void k_scan3() {
    __shared__ int pre;
    int t = threadIdx.x;
    int blk = (blockIdx.x * 256) >> 10;   // superblock index (constant per block)
    if (t == 0) pre = 0;
    __syncthreads();
    int contrib = (t < blk) ? g_bsum[t] : 0;   // blk <= 98 < 256
#pragma unroll
    for (int o = 16; o > 0; o >>= 1) contrib += __shfl_down_sync(0xffffffffu, contrib, o);
    if ((t & 31) == 0 && contrib) atomicAdd(&pre, contrib);
    __syncthreads();
    int i = blockIdx.x * 256 + t;
    if (i < NN) {
        g_rowptr[i + 1] = g_tscan[i] + pre;
        if (i == 0) g_rowptr[0] = 0;
        int d = g_cnt[i];
        g_invdeg[i] = 1.0f / (float)(d > 0 ? d : 1);
        g_cnt[i] = 0;   // restore replay invariant
    }
}
__global__ void k_fill(const int* __restrict__ src, const int* __restrict__ dst) {
    int e = blockIdx.x * blockDim.x + threadIdx.x;
    if (e < NE) {
        int p = g_rowptr[dst[e]] + g_eidx[e];
        g_esrc[p] = src[e];
    }
}

// ---------------- MMA helpers ----------------
__device__ __forceinline__ void mma_f16(float (&c)[4], const uint32_t (&a)[4],
                                        const uint32_t b0, const uint32_t b1) {
    asm volatile(
        "mma.sync.aligned.m16n8k16.row.col.f32.f16.f16.f32 "
        "{%0,%1,%2,%3}, {%4,%5,%6,%7}, {%8,%9}, {%0,%1,%2,%3};\n"
        : "+f"(c[0]), "+f"(c[1]), "+f"(c[2]), "+f"(c[3])
        : "r"(a[0]), "r"(a[1]), "r"(a[2]), "r"(a[3]), "r"(b0), "r"(b1));
}
__device__ __forceinline__ void ldsm_x4(uint32_t (&r)[4], uint32_t addr) {
    asm volatile("ldmatrix.sync.aligned.m8n8.x4.shared.b16 {%0,%1,%2,%3}, [%4];"
                 : "=r"(r[0]), "=r"(r[1]), "=r"(r[2]), "=r"(r[3]) : "r"(addr));
}

// ---------------- unified fp16 2-term dual GEMM (A exact fp16, W = hi+lo), occ-3 ----------------
__global__ __launch_bounds__(256, 3) void k_gemm_f16(
    const __half* __restrict__ xa,
    const __half* __restrict__ wh, const __half* __restrict__ wl,
    const float* __restrict__ bias, int C,
    __half* __restrict__ y, __half* __restrict__ s) {
    extern __shared__ __half smf[];
    __half* As = smf;                 // [128][KP]
    __half* Bh = As + 128 * KP;       // [64][KP]
    __half* Bl = Bh + 64 * KP;

    int tid = threadIdx.x;
    int row0 = blockIdx.x * 128;
    int col0 = blockIdx.y * 64;

    // stage A (raw fp16 copy — exact, no split needed)
    for (int idx = tid; idx < 128 * 16; idx += 256) {
        int r = idx >> 4, k = (idx & 15) << 3;
        int grow = row0 + r;
        uint4 v = make_uint4(0, 0, 0, 0);
        if (grow < NN) v = *(const uint4*)(xa + grow * 128 + k);
        *(uint4*)(As + r * KP + k) = v;
    }
    for (int idx = tid; idx < 64 * 16; idx += 256) {
        int n = idx >> 4, k = (idx & 15) << 3;
        *(uint4*)(Bh + n * KP + k) = *(const uint4*)(wh + (col0 + n) * 128 + k);
        *(uint4*)(Bl + n * KP + k) = *(const uint4*)(wl + (col0 + n) * 128 + k);
    }
    __syncthreads();

    int wid = tid >> 5, lane = tid & 31;
    int mbase = (wid >> 1) * 32;
    int nbase = (wid & 1) * 32;
    int r4 = lane >> 2, tg = lane & 3;

    uint32_t aBase = smem_u32(As);
    uint32_t bBase = smem_u32(Bh);
    uint32_t blBase = smem_u32(Bl);

    int aRow = mbase + (lane & 15);
    int aOff = aRow * KP + ((lane >> 4) << 3);
    int q = lane >> 3;
    int bRow = nbase + ((q >> 1) << 3) + (lane & 7);
    int bOff = bRow * KP + ((q & 1) << 3);

    float acc[2][4][4];
#pragma unroll
    for (int mi = 0; mi < 2; mi++)
#pragma unroll
        for (int ni = 0; ni < 4; ni++)
#pragma unroll
            for (int c = 0; c < 4; c++) acc[mi][ni][c] = 0.f;

#pragma unroll
    for (int kc = 0; kc < 8; kc++) {
        int k0 = kc * 16;
        uint32_t a[2][4];
        ldsm_x4(a[0], aBase + (aOff + k0) * 2);
        ldsm_x4(a[1], aBase + (aOff + 16 * KP + k0) * 2);
        uint32_t bh01[4], bh23[4], bl01[4], bl23[4];
        ldsm_x4(bh01, bBase + (bOff + k0) * 2);
        ldsm_x4(bh23, bBase + (bOff + 16 * KP + k0) * 2);
        ldsm_x4(bl01, blBase + (bOff + k0) * 2);
        ldsm_x4(bl23, blBase + (bOff + 16 * KP + k0) * 2);
#pragma unroll
        for (int mi = 0; mi < 2; mi++) {
            mma_f16(acc[mi][0], a[mi], bh01[0], bh01[1]);
            mma_f16(acc[mi][1], a[mi], bh01[2], bh01[3]);
            mma_f16(acc[mi][2], a[mi], bh23[0], bh23[1]);
            mma_f16(acc[mi][3], a[mi], bh23[2], bh23[3]);
            mma_f16(acc[mi][0], a[mi], bl01[0], bl01[1]);
            mma_f16(acc[mi][1], a[mi], bl01[2], bl01[3]);
            mma_f16(acc[mi][2], a[mi], bl23[0], bl23[1]);
            mma_f16(acc[mi][3], a[mi], bl23[2], bl23[3]);
        }
    }

#pragma unroll
    for (int mi = 0; mi < 2; mi++) {
#pragma unroll
        for (int ni = 0; ni < 4; ni++) {
            int grow0 = row0 + mbase + mi * 16 + r4;
            int cc = col0 + nbase + ni * 8 + tg * 2;
            if (cc >= 2 * C) continue;
#pragma unroll
            for (int half = 0; half < 2; half++) {
                int grow = grow0 + half * 8;
                if (grow >= NN) continue;
                float v0 = acc[mi][ni][half * 2 + 0];
                float v1 = acc[mi][ni][half * 2 + 1];
                if (cc < C) {
                    __half2 hv = __floats2half2_rn(v0, v1);
                    *(uint32_t*)(y + grow * C + cc) = *(uint32_t*)&hv;
                } else {
                    int c = cc - C;
                    __half2 hv = __floats2half2_rn(v0 + bias[c], v1 + bias[c + 1]);
                    *(uint32_t*)(s + grow * C + c) = *(uint32_t*)&hv;
                }
            }
        }
    }
}

// ---------------- gather (fp16 y) + finalize (F=128) -> fp16 activation ----------------
__global__ void k_aggfin128(const uint2* __restrict__ y2, const uint2* __restrict__ s2,
                            uint2* __restrict__ act2) {
    int n = (blockIdx.x * blockDim.x + threadIdx.x) >> 5;
    int lane = threadIdx.x & 31;
    if (n >= NN) return;
    int r0 = g_rowptr[n], r1 = g_rowptr[n + 1];
    float4 acc = make_float4(0.f, 0.f, 0.f, 0.f);
    for (int base = r0; base < r1; base += 32) {
        int idx = base + lane;
        int sid = (idx < r1) ? g_esrc[idx] : 0;
        int m = r1 - base;
        if (m > 32) m = 32;
#pragma unroll 4
        for (int j = 0; j < m; j++) {
            int sn = __shfl_sync(0xffffffffu, sid, j);
            uint2 v = y2[sn * 32 + lane];
            float2 p0 = __half22float2(*(__half2*)&v.x);
            float2 p1 = __half22float2(*(__half2*)&v.y);
            acc.x += p0.x; acc.y += p0.y; acc.z += p1.x; acc.w += p1.y;
        }
    }
    float id = g_invdeg[n];
    uint2 sv = s2[n * 32 + lane];
    float2 s01 = __half22float2(*(__half2*)&sv.x);
    float2 s23 = __half22float2(*(__half2*)&sv.y);
    float4 o;
    o.x = fmaxf(s01.x + acc.x * id, 0.f);
    o.y = fmaxf(s01.y + acc.y * id, 0.f);
    o.z = fmaxf(s23.x + acc.z * id, 0.f);
    o.w = fmaxf(s23.y + acc.w * id, 0.f);
    __half2 a01 = __floats2half2_rn(o.x, o.y);
    __half2 a23 = __floats2half2_rn(o.z, o.w);
    act2[n * 32 + lane] = make_uint2(*(uint32_t*)&a01, *(uint32_t*)&a23);
}

// ---------------- gather (fp16 y) + finalize (F=40) ----------------
__global__ void k_aggfin40(const uint32_t* __restrict__ y32, const uint32_t* __restrict__ s32,
                           float* __restrict__ out) {
    int n = (blockIdx.x * blockDim.x + threadIdx.x) >> 5;
    int lane = threadIdx.x & 31;
    if (n >= NN) return;
    int r0 = g_rowptr[n], r1 = g_rowptr[n + 1];
    float2 acc = make_float2(0.f, 0.f);
    for (int base = r0; base < r1; base += 32) {
        int idx = base + lane;
        int sid = (idx < r1) ? g_esrc[idx] : 0;
        int m = r1 - base;
        if (m > 32) m = 32;
#pragma unroll 4
        for (int j = 0; j < m; j++) {
            int sn = __shfl_sync(0xffffffffu, sid, j);
            if (lane < 20) {
                uint32_t v = y32[sn * 20 + lane];
                float2 p = __half22float2(*(__half2*)&v);
                acc.x += p.x; acc.y += p.y;
            }
        }
    }
    if (lane < 20) {
        float id = g_invdeg[n];
        uint32_t sv = s32[n * 20 + lane];
        float2 sp = __half22float2(*(__half2*)&sv);
        float2 o = make_float2(sp.x + acc.x * id, sp.y + acc.y * id);
        *(float2*)(out + n * 40 + lane * 2) = o;
    }
}

// ---------------- launch ----------------
extern "C" void kernel_launch(void* const* d_in, const int* in_sizes, int n_in,
                              void* d_out, int out_size) {
    const float* feat = (const float*)d_in[0];
    const int* src = (const int*)d_in[1];
    const int* dst = (const int*)d_in[2];
    const float* Ws1 = (const float*)d_in[3];
    const float* Wn1 = (const float*)d_in[4];
    const float* b1  = (const float*)d_in[5];
    const float* Ws2 = (const float*)d_in[6];
    const float* Wn2 = (const float*)d_in[7];
    const float* b2  = (const float*)d_in[8];
    const float* Ws3 = (const float*)d_in[9];
    const float* Wn3 = (const float*)d_in[10];
    const float* b3  = (const float*)d_in[11];
    float* out = (float*)d_out;

    __half *py, *ps, *pa, *pw1h, *pw1l, *pw2h, *pw2l, *pw3h, *pw3l;
    cudaGetSymbolAddress((void**)&py, g_y);
    cudaGetSymbolAddress((void**)&ps, g_s);
    cudaGetSymbolAddress((void**)&pa, g_act);
    cudaGetSymbolAddress((void**)&pw1h, g_w1h);
    cudaGetSymbolAddress((void**)&pw1l, g_w1l);
    cudaGetSymbolAddress((void**)&pw2h, g_w2h);
    cudaGetSymbolAddress((void**)&pw2l, g_w2l);
    cudaGetSymbolAddress((void**)&pw3h, g_w3h);
    cudaGetSymbolAddress((void**)&pw3l, g_w3l);

    const int SMEM_F16 = (128 + 64 + 64) * KP * 2;  // 69632
    cudaFuncSetAttribute(k_gemm_f16, cudaFuncAttributeMaxDynamicSharedMemorySize, SMEM_F16);

    int nbE = (NE + 255) / 256;
    int nbScan = (NN + 1023) / 1024;
    int gRows = (NN + 127) / 128;   // 782
    int gAgg = (NN + 7) / 8;

    // side stream for CSR chain
    cudaStream_t s1;
    cudaStreamCreate(&s1);
    cudaEvent_t e0, e1;
    cudaEventCreateWithFlags(&e0, cudaEventDisableTiming);
    cudaEventCreateWithFlags(&e1, cudaEventDisableTiming);

    cudaEventRecord(e0, 0);
    cudaStreamWaitEvent(s1, e0, 0);

    k_count<<<nbE, 256, 0, s1>>>(dst);
    k_scan1<<<nbScan, 1024, 0, s1>>>();
    k_scan3<<<(NN + 255) / 256, 256, 0, s1>>>();
    k_fill<<<nbE, 256, 0, s1>>>(src, dst);
    cudaEventRecord(e1, s1);

    // main stream: features->fp16 (into g_act) + all weights fp16 hi/lo, then layer-1 GEMM
    k_split<<<(NN * 32 + 255) / 256, 256>>>(
        (const float4*)feat, (uint2*)pa,
        Wn1, Ws1, Wn2, Ws2, Wn3, Ws3,
        pw1h, pw1l, pw2h, pw2l, pw3h, pw3l);
    k_gemm_f16<<<dim3(gRows, 4), 256, SMEM_F16>>>(pa, pw1h, pw1l, b1, 128, py, ps);

    cudaStreamWaitEvent(0, e1, 0);

    k_aggfin128<<<gAgg, 256>>>((const uint2*)py, (const uint2*)ps, (uint2*)pa);
    // layer 2
    k_gemm_f16<<<dim3(gRows, 4), 256, SMEM_F16>>>(pa, pw2h, pw2l, b2, 128, py, ps);
    k_aggfin128<<<gAgg, 256>>>((const uint2*)py, (const uint2*)ps, (uint2*)pa);
    // layer 3
    k_gemm_f16<<<dim3(gRows, 2), 256, SMEM_F16>>>(pa, pw3h, pw3l, b3, 40, py, ps);
    k_aggfin40<<<gAgg, 256>>>((const uint32_t*)py, (const uint32_t*)ps, out);
}